// round 3
// baseline (speedup 1.0000x reference)
#include <cuda_runtime.h>
#include <cstdint>

// SimpleGCNLayer: out = segment_sum(x[src], dst) @ W.T
// Strategy: transform first (y = x @ W.T), then one scatter-add pass with
// vector red.global.add.v4.f32 (fire-and-forget 16B atomics, L2-resident).
// Edge index dtype auto-detected (int32 expected; int64 handled defensively).

#define D 32
#define N_NODES_MAX 100352   // >= 100000, padded

__device__ __align__(16) float g_y[(size_t)N_NODES_MAX * D];
__device__ int g_is64;

// Detect whether edge index is int64 (all high words of first 256 entries == 0)
// or int32 (random indices -> essentially impossible to be all zero).
__global__ void gcn_detect_dtype(const int* __restrict__ ei32, int n_words)
{
    const int lane = threadIdx.x;  // 32 threads
    int allzero = 1;
    for (int k = lane; k < 256; k += 32) {
        const int odd = 2 * k + 1;
        if (odd < n_words && ei32[odd] != 0) allzero = 0;
    }
    allzero = __all_sync(0xffffffffu, allzero);
    if (lane == 0) g_is64 = allzero;
}

// One warp per node: y[n][o] = sum_i x[n][i] * W[o][i]; also zero d_out.
__global__ void __launch_bounds__(256) gcn_transform_zero(
    const float* __restrict__ x,
    const float* __restrict__ W,
    float* __restrict__ out,
    int n_nodes)
{
    __shared__ float Wsh[D][D + 1];   // padded: conflict-free Wsh[lane][i]
    const int tid = threadIdx.x;
#pragma unroll
    for (int k = 0; k < 4; k++) {
        const int i = tid + k * 256;
        Wsh[i >> 5][i & 31] = W[i];
    }
    __syncthreads();

    const int lane = tid & 31;
    const int node = blockIdx.x * 8 + (tid >> 5);
    if (node >= n_nodes) return;

    const float xv = x[(size_t)node * D + lane];   // coalesced 128B per warp
    float acc = 0.0f;
#pragma unroll
    for (int i = 0; i < D; i++) {
        const float xi = __shfl_sync(0xffffffffu, xv, i);
        acc = fmaf(xi, Wsh[lane][i], acc);
    }
    g_y[(size_t)node * D + lane] = acc;
    out[(size_t)node * D + lane] = 0.0f;   // d_out is poisoned; we accumulate into it
}

// 8 threads per edge; each thread moves one float4 (coalesced) and issues a
// vector reduction (no return value -> REDG, max throughput).
__global__ void __launch_bounds__(256) gcn_scatter(
    const int* __restrict__ ei32,   // [2, n_edges]: src row then dst row
    float* __restrict__ out,
    int n_edges, int n_nodes)
{
    const long long t = (long long)blockIdx.x * 256 + threadIdx.x;
    const int edge = (int)(t >> 3);
    if (edge >= n_edges) return;
    const int sub = (int)(t & 7);

    int s, d;
    if (g_is64) {   // uniform branch
        const long long* ei64 = (const long long*)ei32;
        s = (int)__ldg(ei64 + edge);
        d = (int)__ldg(ei64 + n_edges + edge);
    } else {
        s = __ldg(ei32 + edge);
        d = __ldg(ei32 + n_edges + edge);
    }
    // Safety: wrong index must never fault; it would surface as rel_err instead.
    if ((unsigned)s >= (unsigned)n_nodes || (unsigned)d >= (unsigned)n_nodes) return;

    const float4 v = *reinterpret_cast<const float4*>(g_y + (size_t)s * D + sub * 4);
    float* p = out + (size_t)d * D + sub * 4;
    asm volatile("red.global.add.v4.f32 [%0], {%1, %2, %3, %4};"
                 :: "l"(p), "f"(v.x), "f"(v.y), "f"(v.z), "f"(v.w)
                 : "memory");
}

extern "C" void kernel_launch(void* const* d_in, const int* in_sizes, int n_in,
                              void* d_out, int out_size)
{
    const float* x    = (const float*)d_in[0];   // [N, 32] f32
    const int*   ei32 = (const int*)d_in[1];     // [2, E] int32 (or int64, detected)
    const float* W    = (const float*)d_in[2];   // [32, 32] f32
    float* out = (float*)d_out;                  // [N, 32] f32

    const int n_nodes = in_sizes[0] / D;
    const int n_edges = in_sizes[1] / 2;

    // Phase 0: dtype probe (1 warp, negligible).
    gcn_detect_dtype<<<1, 32>>>(ei32, in_sizes[1]);

    // Phase 1: y = x @ W.T into scratch; zero out.
    const int tblocks = (n_nodes + 7) / 8;
    gcn_transform_zero<<<tblocks, 256>>>(x, W, out, n_nodes);

    // Phase 2: out[dst] += y[src] via vector atomics.
    const long long total = (long long)n_edges * 8;
    const int sblocks = (int)((total + 255) / 256);
    gcn_scatter<<<sblocks, 256>>>(ei32, out, n_edges, n_nodes);
}

// round 4
// speedup vs baseline: 1.0430x; 1.0430x over previous
#include <cuda_runtime.h>
#include <cstdint>

// SimpleGCNLayer: out = segment_sum(x[src], dst) @ W.T
// Strategy: transform first (y = x @ W.T), then one scatter-add pass with
// vector red.global.add.v4.f32 (fire-and-forget 16B atomics, L2-resident).
// int64-vs-int32 probe folded into the transform kernel (no extra launch).

#define D 32
#define N_NODES_MAX 100352   // >= 100000, padded

__device__ __align__(16) float g_y[(size_t)N_NODES_MAX * D];
__device__ int g_is64;

// One warp per node: y[n][o] = sum_i x[n][i] * W[o][i]; also zero d_out.
// Block 0 / warp 0 additionally probes the edge-index dtype: for int64 data
// with values < 2^31, every odd 32-bit word is 0; for int32 indices the odds
// of 256 consecutive zero odd-words is ~0.
__global__ void __launch_bounds__(256) gcn_transform_zero(
    const float* __restrict__ x,
    const float* __restrict__ W,
    float* __restrict__ out,
    const int* __restrict__ ei32,
    int ei_words,
    int n_nodes)
{
    __shared__ float Wsh[D][D + 1];   // padded: conflict-free Wsh[lane][i]
    const int tid = threadIdx.x;
#pragma unroll
    for (int k = 0; k < 4; k++) {
        const int i = tid + k * 256;
        Wsh[i >> 5][i & 31] = W[i];
    }

    if (blockIdx.x == 0 && tid < 32) {   // dtype probe, overlapped with grid
        int allzero = 1;
        for (int k = tid; k < 256; k += 32) {
            const int odd = 2 * k + 1;
            if (odd < ei_words && ei32[odd] != 0) allzero = 0;
        }
        allzero = __all_sync(0xffffffffu, allzero);
        if (tid == 0) g_is64 = allzero;
    }
    __syncthreads();

    const int lane = tid & 31;
    const int node = blockIdx.x * 8 + (tid >> 5);
    if (node >= n_nodes) return;

    const float xv = x[(size_t)node * D + lane];   // coalesced 128B per warp
    float acc = 0.0f;
#pragma unroll
    for (int i = 0; i < D; i++) {
        const float xi = __shfl_sync(0xffffffffu, xv, i);
        acc = fmaf(xi, Wsh[lane][i], acc);
    }
    g_y[(size_t)node * D + lane] = acc;
    out[(size_t)node * D + lane] = 0.0f;   // d_out is poisoned; we accumulate into it
}

// 8 threads per edge; each thread moves one float4 (coalesced) and issues a
// vector reduction (no return value -> REDG, max throughput).
__global__ void __launch_bounds__(256) gcn_scatter(
    const int* __restrict__ ei32,   // [2, n_edges]: src row then dst row
    float* __restrict__ out,
    int n_edges, int n_nodes)
{
    const long long t = (long long)blockIdx.x * 256 + threadIdx.x;
    const int edge = (int)(t >> 3);
    if (edge >= n_edges) return;
    const int sub = (int)(t & 7);

    int s, d;
    if (g_is64) {   // uniform branch (probe result from transform kernel)
        const long long* ei64 = (const long long*)ei32;
        s = (int)__ldg(ei64 + edge);
        d = (int)__ldg(ei64 + n_edges + edge);
    } else {
        s = __ldg(ei32 + edge);
        d = __ldg(ei32 + n_edges + edge);
    }
    // Safety: a wrong index must never fault; it surfaces as rel_err instead.
    if ((unsigned)s >= (unsigned)n_nodes || (unsigned)d >= (unsigned)n_nodes) return;

    const float4 v = *reinterpret_cast<const float4*>(g_y + (size_t)s * D + sub * 4);
    float* p = out + (size_t)d * D + sub * 4;
    asm volatile("red.global.add.v4.f32 [%0], {%1, %2, %3, %4};"
                 :: "l"(p), "f"(v.x), "f"(v.y), "f"(v.z), "f"(v.w)
                 : "memory");
}

extern "C" void kernel_launch(void* const* d_in, const int* in_sizes, int n_in,
                              void* d_out, int out_size)
{
    const float* x    = (const float*)d_in[0];   // [N, 32] f32
    const int*   ei32 = (const int*)d_in[1];     // [2, E] int32 (int64 auto-detected)
    const float* W    = (const float*)d_in[2];   // [32, 32] f32
    float* out = (float*)d_out;                  // [N, 32] f32

    const int n_nodes = in_sizes[0] / D;
    const int n_edges = in_sizes[1] / 2;

    // Phase 1: y = x @ W.T into scratch; zero out; probe dtype (block 0).
    const int tblocks = (n_nodes + 7) / 8;
    gcn_transform_zero<<<tblocks, 256>>>(x, W, out, ei32, in_sizes[1], n_nodes);

    // Phase 2: out[dst] += y[src] via vector atomics.
    const long long total = (long long)n_edges * 8;
    const int sblocks = (int)((total + 255) / 256);
    gcn_scatter<<<sblocks, 256>>>(ei32, out, n_edges, n_nodes);
}

// round 5
// speedup vs baseline: 1.0696x; 1.0255x over previous
#include <cuda_runtime.h>
#include <cstdint>

// SimpleGCNLayer: out = segment_sum(x[src], dst) @ W.T
// Transform-first + vector-RED scatter. Scatter is latency-bound (ncu R4:
// L1=57%, issue=30%, occ=80%, nothing saturated) -> batch 8 edges per thread
// for MLP=8 on the random gathers.

#define D 32
#define N_NODES_MAX 100352   // >= 100000, padded

__device__ __align__(16) float g_y[(size_t)N_NODES_MAX * D];
__device__ int g_is64;

// One warp per node: y[n][o] = sum_i x[n][i] * W[o][i]; also zero d_out.
// Block 0 / warp 0 probes the edge-index dtype (int64 => odd words all 0).
__global__ void __launch_bounds__(256) gcn_transform_zero(
    const float* __restrict__ x,
    const float* __restrict__ W,
    float* __restrict__ out,
    const int* __restrict__ ei32,
    int ei_words,
    int n_nodes)
{
    __shared__ float Wsh[D][D + 1];
    const int tid = threadIdx.x;
#pragma unroll
    for (int k = 0; k < 4; k++) {
        const int i = tid + k * 256;
        Wsh[i >> 5][i & 31] = W[i];
    }

    if (blockIdx.x == 0 && tid < 32) {   // dtype probe, overlapped with grid
        int allzero = 1;
        for (int k = tid; k < 256; k += 32) {
            const int odd = 2 * k + 1;
            if (odd < ei_words && ei32[odd] != 0) allzero = 0;
        }
        allzero = __all_sync(0xffffffffu, allzero);
        if (tid == 0) g_is64 = allzero;
    }
    __syncthreads();

    const int lane = tid & 31;
    const int node = blockIdx.x * 8 + (tid >> 5);
    if (node >= n_nodes) return;

    const float xv = x[(size_t)node * D + lane];
    float acc = 0.0f;
#pragma unroll
    for (int i = 0; i < D; i++) {
        const float xi = __shfl_sync(0xffffffffu, xv, i);
        acc = fmaf(xi, Wsh[lane][i], acc);
    }
    g_y[(size_t)node * D + lane] = acc;
    out[(size_t)node * D + lane] = 0.0f;
}

// One warp handles 32 edges: each lane loads the indices of one edge
// (coalesced), shuffles them out, then each thread gathers 8 float4s
// (8 independent LDG.128 chains -> MLP=8) and fires 8 vector REDs.
__global__ void __launch_bounds__(256) gcn_scatter(
    const int* __restrict__ ei32,   // [2, n_edges]: src row then dst row
    float* __restrict__ out,
    int n_edges, int n_nodes)
{
    const int lane = threadIdx.x & 31;
    const long long gw = (long long)blockIdx.x * 8 + (threadIdx.x >> 5);
    const long long base = gw * 32;
    if (base >= n_edges) return;

    // Coalesced index load: lane's edge = base + lane.
    int s_all = 0, d_all = 0;
    const long long e = base + lane;
    if (e < n_edges) {
        if (g_is64) {   // uniform branch
            const long long* ei64 = (const long long*)ei32;
            s_all = (int)__ldg(ei64 + e);
            d_all = (int)__ldg(ei64 + n_edges + e);
        } else {
            s_all = __ldg(ei32 + e);
            d_all = __ldg(ei32 + (long long)n_edges + e);
        }
    }

    const int sub4 = (lane & 7) * 4;   // float4 lane within the 32-float row
    float4 v[8];
    int    dd[8];
    bool   ok[8];

#pragma unroll
    for (int u = 0; u < 8; u++) {
        const int eiw = u * 4 + (lane >> 3);        // edge-in-warp 0..31
        const int s = __shfl_sync(0xffffffffu, s_all, eiw);
        dd[u]       = __shfl_sync(0xffffffffu, d_all, eiw);
        ok[u] = (base + eiw < n_edges) &&
                (unsigned)s < (unsigned)n_nodes &&
                (unsigned)dd[u] < (unsigned)n_nodes;
        // Predicated gather; 8 of these issue back-to-back (MLP=8).
        v[u] = ok[u] ? *reinterpret_cast<const float4*>(g_y + (size_t)s * D + sub4)
                     : make_float4(0.f, 0.f, 0.f, 0.f);
    }

#pragma unroll
    for (int u = 0; u < 8; u++) {
        if (ok[u]) {
            float* p = out + (size_t)dd[u] * D + sub4;
            asm volatile("red.global.add.v4.f32 [%0], {%1, %2, %3, %4};"
                         :: "l"(p), "f"(v[u].x), "f"(v[u].y), "f"(v[u].z), "f"(v[u].w)
                         : "memory");
        }
    }
}

extern "C" void kernel_launch(void* const* d_in, const int* in_sizes, int n_in,
                              void* d_out, int out_size)
{
    const float* x    = (const float*)d_in[0];   // [N, 32] f32
    const int*   ei32 = (const int*)d_in[1];     // [2, E] int32 (int64 auto-detected)
    const float* W    = (const float*)d_in[2];   // [32, 32] f32
    float* out = (float*)d_out;                  // [N, 32] f32

    const int n_nodes = in_sizes[0] / D;
    const int n_edges = in_sizes[1] / 2;

    // Phase 1: y = x @ W.T into scratch; zero out; probe dtype (block 0).
    const int tblocks = (n_nodes + 7) / 8;
    gcn_transform_zero<<<tblocks, 256>>>(x, W, out, ei32, in_sizes[1], n_nodes);

    // Phase 2: out[dst] += y[src]; 32 edges per warp, 8 warps per block.
    const long long warps = ((long long)n_edges + 31) / 32;
    const int sblocks = (int)((warps + 7) / 8);
    gcn_scatter<<<sblocks, 256>>>(ei32, out, n_edges, n_nodes);
}

// round 7
// speedup vs baseline: 1.4237x; 1.3311x over previous
#include <cuda_runtime.h>
#include <cstdint>

// SimpleGCNLayer: out = segment_sum(x[src], dst) @ W.T
// Transform-first (register-tiled, no shuffles) + vector-RED scatter (MLP=8).

#define D 32
#define N_NODES_MAX 100352
#define TNODES 128          // nodes per transform block
#define XS_STRIDE 36        // smem row stride: %32==4 -> conflict-free, 16B aligned

__device__ __align__(16) float g_y[(size_t)N_NODES_MAX * D];
__device__ int g_is64;

// Block = 256 threads = 128 nodes. Thread (g = tid>>3, q = tid&7) owns
// 4 nodes (g, g+32, g+64, g+96) x 4 outputs (4q..4q+3): 16 accumulators.
// Block 0 / warp 0 also probes the edge-index dtype (int64 => odd words all 0).
__global__ void __launch_bounds__(256) gcn_transform_zero(
    const float* __restrict__ x,
    const float* __restrict__ W,
    float* __restrict__ out,
    const int* __restrict__ ei32,
    int ei_words,
    int n_nodes)
{
    __shared__ float xs[TNODES * XS_STRIDE];   // x tile, padded rows
    __shared__ float wt[D * D];                // W transposed: wt[i*32+o] = W[o][i]

    const int tid = threadIdx.x;
    const int node_base = blockIdx.x * TNODES;

    if (blockIdx.x == 0 && tid < 32) {   // dtype probe, overlapped with grid
        int allzero = 1;
        for (int k = tid; k < 256; k += 32) {
            const int odd = 2 * k + 1;
            if (odd < ei_words && ei32[odd] != 0) allzero = 0;
        }
        allzero = __all_sync(0xffffffffu, allzero);
        if (tid == 0) g_is64 = allzero;
    }

    // Stage W transposed: wt[i][o] = W[o][i].
#pragma unroll
    for (int k = 0; k < 4; k++) {
        const int idx = tid + k * 256;        // o = idx>>5, i = idx&31
        wt[(idx & 31) * D + (idx >> 5)] = W[idx];
    }
    // Stage x tile (float4-coalesced).
#pragma unroll
    for (int k = 0; k < 4; k++) {
        const int idx4 = tid + k * 256;       // 1024 float4s = 128 rows x 8
        const int nl = idx4 >> 3, i4 = (idx4 & 7) * 4;
        float4 xv = make_float4(0.f, 0.f, 0.f, 0.f);
        if (node_base + nl < n_nodes)
            xv = *reinterpret_cast<const float4*>(x + (size_t)(node_base + nl) * D + i4);
        *reinterpret_cast<float4*>(xs + nl * XS_STRIDE + i4) = xv;
    }
    __syncthreads();

    const int q  = tid & 7;          // output quad: columns 4q..4q+3
    const int g  = tid >> 3;         // node group 0..31
    float4 acc[4] = {};

#pragma unroll
    for (int i = 0; i < D; i++) {
        const float4 w4 = *reinterpret_cast<const float4*>(wt + i * D + 4 * q);
#pragma unroll
        for (int r = 0; r < 4; r++) {
            const float xv = xs[(g + 32 * r) * XS_STRIDE + i];   // broadcast LDS
            acc[r].x = fmaf(xv, w4.x, acc[r].x);
            acc[r].y = fmaf(xv, w4.y, acc[r].y);
            acc[r].z = fmaf(xv, w4.z, acc[r].z);
            acc[r].w = fmaf(xv, w4.w, acc[r].w);
        }
    }

#pragma unroll
    for (int r = 0; r < 4; r++) {
        const int node = node_base + g + 32 * r;
        if (node < n_nodes) {
            *reinterpret_cast<float4*>(g_y + (size_t)node * D + 4 * q) = acc[r];
            *reinterpret_cast<float4*>(out + (size_t)node * D + 4 * q) =
                make_float4(0.f, 0.f, 0.f, 0.f);   // d_out poisoned; zero it
        }
    }
}

// One warp handles 32 edges: coalesced index load + shuffle distribution,
// then 8 independent float4 gathers per thread (MLP=8) and 8 vector REDs.
__global__ void __launch_bounds__(256) gcn_scatter(
    const int* __restrict__ ei32,   // [2, n_edges]: src row then dst row
    float* __restrict__ out,
    int n_edges, int n_nodes)
{
    const int lane = threadIdx.x & 31;
    const long long base = ((long long)blockIdx.x * 8 + (threadIdx.x >> 5)) * 32;
    if (base >= n_edges) return;

    int s_all = 0, d_all = 0;
    const long long e = base + lane;
    if (e < n_edges) {
        if (g_is64) {   // uniform branch
            const long long* ei64 = (const long long*)ei32;
            s_all = (int)__ldg(ei64 + e);
            d_all = (int)__ldg(ei64 + n_edges + e);
        } else {
            s_all = __ldg(ei32 + e);
            d_all = __ldg(ei32 + (long long)n_edges + e);
        }
    }

    const int sub4 = (lane & 7) * 4;
    float4 v[8];
    int    dd[8];

#pragma unroll
    for (int u = 0; u < 8; u++) {
        const int eiw = u * 4 + (lane >> 3);
        const int s = __shfl_sync(0xffffffffu, s_all, eiw);
        dd[u]       = __shfl_sync(0xffffffffu, d_all, eiw);
        const bool ok = (base + eiw < n_edges) && (unsigned)s < (unsigned)n_nodes;
        v[u] = ok ? *reinterpret_cast<const float4*>(g_y + (size_t)s * D + sub4)
                  : make_float4(0.f, 0.f, 0.f, 0.f);
    }

#pragma unroll
    for (int u = 0; u < 8; u++) {
        const int eiw = u * 4 + (lane >> 3);
        if ((base + eiw < n_edges) && (unsigned)dd[u] < (unsigned)n_nodes) {
            float* p = out + (size_t)dd[u] * D + sub4;
            asm volatile("red.global.add.v4.f32 [%0], {%1, %2, %3, %4};"
                         :: "l"(p), "f"(v[u].x), "f"(v[u].y), "f"(v[u].z), "f"(v[u].w)
                         : "memory");
        }
    }
}

extern "C" void kernel_launch(void* const* d_in, const int* in_sizes, int n_in,
                              void* d_out, int out_size)
{
    const float* x    = (const float*)d_in[0];   // [N, 32] f32
    const int*   ei32 = (const int*)d_in[1];     // [2, E] int32 (int64 auto-detected)
    const float* W    = (const float*)d_in[2];   // [32, 32] f32
    float* out = (float*)d_out;                  // [N, 32] f32

    const int n_nodes = in_sizes[0] / D;
    const int n_edges = in_sizes[1] / 2;

    const int tblocks = (n_nodes + TNODES - 1) / TNODES;
    gcn_transform_zero<<<tblocks, 256>>>(x, W, out, ei32, in_sizes[1], n_nodes);

    const long long warps = ((long long)n_edges + 31) / 32;
    const int sblocks = (int)((warps + 7) / 8);
    gcn_scatter<<<sblocks, 256>>>(ei32, out, n_edges, n_nodes);
}